// round 7
// baseline (speedup 1.0000x reference)
#include <cuda_runtime.h>
#include <cuda_bf16.h>
#include <cstdint>
#include <cstring>

// ---------------- constants ----------------
constexpr int NP = 8192;
constexpr int WTOT = 23592960;
constexpr int PER_BLK_W = 737280;
constexpr size_t WP_PER_BLK = 2949120;
constexpr size_t MP_PER_BLK = 147456;

// ---------------- device scratch ----------------
__device__ char g_wpc[32 * WP_PER_BLK];
__device__ char g_mpc[32 * MP_PER_BLK];
__device__ float g_Xa[NP * 192], g_Xb[NP * 192];
__device__ __nv_bfloat16 g_XaH[NP * 192], g_XaL[NP * 192];
__device__ __nv_bfloat16 g_XbH[NP * 192], g_XbL[NP * 192];
__device__ __nv_bfloat16 g_T1H[NP * 128], g_T1L[NP * 128];
__device__ __nv_bfloat16 g_T2H[NP * 128], g_T2L[NP * 128];

// ---------------- helpers ----------------
__device__ __forceinline__ uint32_t smem_u32(const void* p) {
    uint32_t a;
    asm("{ .reg .u64 t; cvta.to.shared.u64 t, %1; cvt.u32.u64 %0, t; }" : "=r"(a) : "l"(p));
    return a;
}
__device__ __forceinline__ unsigned short f2bf(float v) {
    __nv_bfloat16 b = __float2bfloat16(v);
    unsigned short u; memcpy(&u, &b, 2);
    return u;
}
__device__ __forceinline__ float bf2f(unsigned short u) {
    __nv_bfloat16 b; memcpy(&b, &u, 2);
    return __bfloat162float(b);
}
__device__ __forceinline__ void ldm4(uint32_t* r, uint32_t addr) {
    asm volatile("ldmatrix.sync.aligned.m8n8.x4.shared.b16 {%0,%1,%2,%3}, [%4];"
        : "=r"(r[0]), "=r"(r[1]), "=r"(r[2]), "=r"(r[3]) : "r"(addr));
}
__device__ __forceinline__ void ldm2(uint32_t* r, uint32_t addr) {
    asm volatile("ldmatrix.sync.aligned.m8n8.x2.shared.b16 {%0,%1}, [%2];"
        : "=r"(r[0]), "=r"(r[1]) : "r"(addr));
}
__device__ __forceinline__ void mma16816(float* d, const uint32_t* a, uint32_t b0, uint32_t b1) {
    asm volatile("mma.sync.aligned.m16n8k16.row.col.f32.bf16.bf16.f32 "
        "{%0,%1,%2,%3},{%4,%5,%6,%7},{%8,%9},{%0,%1,%2,%3};"
        : "+f"(d[0]), "+f"(d[1]), "+f"(d[2]), "+f"(d[3])
        : "r"(a[0]), "r"(a[1]), "r"(a[2]), "r"(a[3]), "r"(b0), "r"(b1));
}
__device__ __forceinline__ void cpa16(uint32_t dst, const void* src, uint32_t srcsz) {
    asm volatile("cp.async.cg.shared.global [%0], [%1], 16, %2;"
        :: "r"(dst), "l"(src), "r"(srcsz) : "memory");
}
#define CP_COMMIT() asm volatile("cp.async.commit_group;" ::: "memory")
#define CP_WAIT1()  asm volatile("cp.async.wait_group 1;" ::: "memory")

// ---------------- weight prepack (convs), dst-indexed ----------------
__global__ void k_wp(const float* __restrict__ wf) {
    int idx = blockIdx.x * 256 + threadIdx.x;
    if (idx >= WTOT) return;
    int blk = idx / PER_BLK_W;
    int r = idx - blk * PER_BLK_W;
    const int starts[6] = {0, 110592, 258048, 368640, 479232, 626688};
    const size_t pre[6] = {0, 442368, 1032192, 1474560, 1916928, 2506752};
    int j = 0;
#pragma unroll
    for (int t = 1; t < 6; t++) if (r >= starts[t]) j = t;
    int off = r - starts[j];
    int oc = ((j % 3) == 2) ? 96 : 128;
    int ic = ((j % 3) == 0) ? 96 : 128;
    int unitE = oc * 32;
    int u = off / unitE;
    int wi = off - u * unitE;
    int o = wi >> 5, cl = wi & 31;
    int nch = ic >> 5;
    int tap = u / nch, chk = u - tap * nch;
    int c = chk * 32 + cl;
    float v = wf[(size_t)blk * PER_BLK_W + starts[j] + (size_t)(o * ic + c) * 9 + tap];
    unsigned short hb = f2bf(v);
    unsigned short lb = f2bf(v - bf2f(hb));
    size_t base = (size_t)blk * WP_PER_BLK + pre[j] + (size_t)u * (oc * 128);
    *(unsigned short*)(g_wpc + base + (size_t)wi * 2) = hb;
    *(unsigned short*)(g_wpc + base + (size_t)oc * 64 + (size_t)wi * 2) = lb;
}

// ---------------- mixing prepack ----------------
__global__ void k_mp(const float* __restrict__ m) {
    int idx = blockIdx.x * 256 + threadIdx.x;
    if (idx >= 32 * 36864) return;
    int blk = idx / 36864;
    int r = idx - blk * 36864;
    int u = r / 6144;
    int wi = r - u * 6144;
    int o = wi >> 5, cl = wi & 31;
    int c = u * 32 + cl;
    float v = m[(size_t)blk * 36864 + o * 192 + c];
    unsigned short hb = f2bf(v);
    unsigned short lb = f2bf(v - bf2f(hb));
    size_t base = (size_t)blk * MP_PER_BLK + (size_t)u * 24576;
    *(unsigned short*)(g_mpc + base + (size_t)wi * 2) = hb;
    *(unsigned short*)(g_mpc + base + 12288 + (size_t)wi * 2) = lb;
}

// ---------------- normalize + permute + space_to_depth -> NHWC ----------------
__global__ void k_pre(const float* __restrict__ x, const float* __restrict__ mu,
                      const float* __restrict__ sigma, const int* __restrict__ perm,
                      float* __restrict__ Xo, __nv_bfloat16* __restrict__ XoH,
                      __nv_bfloat16* __restrict__ XoL) {
    int idx = blockIdx.x * 256 + threadIdx.x;
    if (idx >= NP * 192) return;
    int ch = idx % 192;
    int p = idx / 192;
    int w = p & 31, h = (p >> 5) & 31, b = p >> 10;
    int c = ch >> 6, r = ch & 63;
    int bi = r >> 3, bj = r & 7;
    int flat = (h * 8 + bi) * 256 + (w * 8 + bj);
    int src = perm[c * 65536 + flat];
    float v = (x[(b * 3 + c) * 65536 + src] - mu[c]) / sigma[c];
    Xo[idx] = v;
    unsigned short hb = f2bf(v);
    XoH[idx] = *(__nv_bfloat16*)&hb;
    unsigned short lb = f2bf(v - bf2f(hb));
    XoL[idx] = *(__nv_bfloat16*)&lb;
}

// ---------------- final NHWC -> NCHW ----------------
__global__ void k_post(const float* __restrict__ X, float* __restrict__ out) {
    int idx = blockIdx.x * 256 + threadIdx.x;
    if (idx >= NP * 192) return;
    int w = idx & 31;
    int h = (idx >> 5) & 31;
    int ch = (idx >> 10) % 192;
    int b = idx / (192 * 1024);
    out[idx] = X[(((b * 32 + h) * 32 + w) * 192) + ch];
}

// ---------------- warp-mma bf16x3 implicit-GEMM conv ----------------
// CTA = 32 positions (one image row) x full OC -> grid 256 (2 CTAs/SM).
// 256 threads, 8 warps as 2M x 4N. Triple-buffered cp.async, 1 sync/stage.
template <int IC, int OC, int KS, bool RELU, bool ADDIN>
__global__ __launch_bounds__(256, 2) void k_mma(
    const __nv_bfloat16* __restrict__ inH, const __nv_bfloat16* __restrict__ inL,
    int in_stride,
    const char* __restrict__ wp,
    const float* __restrict__ bias,
    const float* __restrict__ addp, int add_stride,
    float* __restrict__ out,
    __nv_bfloat16* __restrict__ outH, __nv_bfloat16* __restrict__ outL,
    int out_stride)
{
    constexpr int NCH = IC / 32;
    constexpr int NST = KS * KS * NCH;
    constexpr int NT = OC / 32;          // n8-tiles per warp (warp N = OC/4)
    constexpr int PH = KS / 2;
    constexpr int LDA = 40;              // padded bf16 row stride (80 B)
    constexpr int ASZ = 32 * LDA;        // ush per A buffer
    constexpr int BSZ = OC * LDA;        // ush per B buffer
    constexpr int unitB = OC * 128;

    extern __shared__ __align__(16) unsigned short smem[];
    unsigned short* Ah = smem;                 // [3][32][LDA]
    unsigned short* Al = Ah + 3 * ASZ;
    unsigned short* Bh = Al + 3 * ASZ;         // [3][OC][LDA]
    unsigned short* Bl = Bh + 3 * BSZ;

    const int tid = threadIdx.x;
    const int wid = tid >> 5, lane = tid & 31;
    const int wm = wid & 1, wn = wid >> 1;
    const int p0 = blockIdx.x * 32;
    const int b = p0 >> 10;
    const int h0 = (p0 >> 5) & 31;

    // A staging: threads 0-127 stage Ah, 128-255 stage Al; (row, quad) map.
    const int at = tid & 127;
    const int ar = at >> 2;              // 0..31 = w position
    const int ac = (at & 3) * 8;
    const int alo = tid >> 7;            // 0 -> hi, 1 -> lo

    float acc[NT][4];
#pragma unroll
    for (int j = 0; j < NT; j++)
#pragma unroll
        for (int q = 0; q < 4; q++) acc[j][q] = 0.f;

    const uint32_t sA = smem_u32(alo ? Al : Ah) + (uint32_t)(ar * LDA + ac) * 2;
    const uint32_t sBh = smem_u32(Bh);
    const uint32_t sBl = smem_u32(Bl);
    const __nv_bfloat16* inA = alo ? inL : inH;

    auto issue = [&](int s, int buf) {
        const int tap = s / NCH, ch = s - tap * NCH;
        const int ky = tap / KS, kx = tap - ky * KS;
        const int hh = h0 + ky - PH, ww = ar + kx - PH;
        const bool ok = (hh >= 0) && (hh < 32) && (ww >= 0) && (ww < 32);
        const size_t aoff = ok ? ((size_t)(((b << 5) + hh) * 32 + ww) * in_stride + ch * 32 + ac) : 0;
        const uint32_t sz = ok ? 16u : 0u;
        cpa16(sA + (uint32_t)buf * ASZ * 2, inA + aoff, sz);
        const char* bu = wp + (size_t)s * unitB;
#pragma unroll
        for (int i = tid; i < OC * 4; i += 256) {
            int rr = i >> 2, q = i & 3;
            uint32_t doff = (uint32_t)(buf * BSZ + rr * LDA + q * 8) * 2;
            cpa16(sBh + doff, bu + (size_t)i * 16, 16);
            cpa16(sBl + doff, bu + (size_t)OC * 64 + (size_t)i * 16, 16);
        }
        CP_COMMIT();
    };

    issue(0, 0);
    issue(1, 1);

    for (int s = 0; s < NST; s++) {
        const int buf0 = s - (s / 3) * 3;
        CP_WAIT1();
        __syncthreads();
        if (s + 2 < NST) {
            int b2 = (s + 2) - ((s + 2) / 3) * 3;
            issue(s + 2, b2);
        } else {
            CP_COMMIT();
        }

        const uint32_t aAh = smem_u32(Ah + buf0 * ASZ);
        const uint32_t aAl = smem_u32(Al + buf0 * ASZ);
        const uint32_t aBh = smem_u32(Bh + buf0 * BSZ);
        const uint32_t aBl = smem_u32(Bl + buf0 * BSZ);

#pragma unroll
        for (int ks = 0; ks < 2; ks++) {
            uint32_t ahf[4], alf[4];
            {
                uint32_t ro = (uint32_t)(wm * 16 + (lane & 15)) * (LDA * 2)
                            + (uint32_t)(ks * 2 + (lane >> 4)) * 16;
                ldm4(ahf, aAh + ro);
                ldm4(alf, aAl + ro);
            }
#pragma unroll
            for (int np = 0; np < NT / 2; np++) {
                uint32_t ro = (uint32_t)(wn * (OC / 4) + np * 16 + (lane & 15)) * (LDA * 2)
                            + (uint32_t)(ks * 2 + (lane >> 4)) * 16;
                uint32_t bh4[4], bl4[4];
                ldm4(bh4, aBh + ro);
                ldm4(bl4, aBl + ro);
#pragma unroll
                for (int sub = 0; sub < 2; sub++) {
                    float* d = acc[np * 2 + sub];
                    mma16816(d, ahf, bh4[sub], bh4[sub + 2]);
                    mma16816(d, ahf, bl4[sub], bl4[sub + 2]);
                    mma16816(d, alf, bh4[sub], bh4[sub + 2]);
                }
            }
            if (NT & 1) {
                uint32_t ro = (uint32_t)(wn * (OC / 4) + (NT - 1) * 8 + (lane & 7)) * (LDA * 2)
                            + (uint32_t)(ks * 2 + ((lane >> 3) & 1)) * 16;
                uint32_t bh2[2], bl2[2];
                ldm2(bh2, aBh + ro);
                ldm2(bl2, aBl + ro);
                float* d = acc[NT - 1];
                mma16816(d, ahf, bh2[0], bh2[1]);
                mma16816(d, ahf, bl2[0], bl2[1]);
                mma16816(d, alf, bh2[0], bh2[1]);
            }
        }
    }

    // ---- epilogue ----
    const int l4 = lane >> 2, l2 = (lane & 3) * 2;
#pragma unroll
    for (int nt = 0; nt < NT; nt++) {
        const int col = wn * (OC / 4) + nt * 8 + l2;
        float b0 = 0.f, b1 = 0.f;
        if (bias) { b0 = bias[col]; b1 = bias[col + 1]; }
        const int pr = p0 + wm * 16 + l4;
        float* d = acc[nt];
        float v0 = d[0] + b0, v1 = d[1] + b1, v2 = d[2] + b0, v3 = d[3] + b1;
        if (RELU) {
            v0 = fmaxf(v0, 0.f); v1 = fmaxf(v1, 0.f);
            v2 = fmaxf(v2, 0.f); v3 = fmaxf(v3, 0.f);
        }
        if (ADDIN) {
            float2 a0 = *(const float2*)(addp + (size_t)pr * add_stride + col);
            float2 a1 = *(const float2*)(addp + (size_t)(pr + 8) * add_stride + col);
            v0 += a0.x; v1 += a0.y; v2 += a1.x; v3 += a1.y;
        }
        if (out) {
            *(float2*)(out + (size_t)pr * out_stride + col) = make_float2(v0, v1);
            *(float2*)(out + (size_t)(pr + 8) * out_stride + col) = make_float2(v2, v3);
        }
        __nv_bfloat162 h01 = __float22bfloat162_rn(make_float2(v0, v1));
        __nv_bfloat162 h23 = __float22bfloat162_rn(make_float2(v2, v3));
        float2 f01 = __bfloat1622float2(h01);
        float2 f23 = __bfloat1622float2(h23);
        __nv_bfloat162 l01 = __float22bfloat162_rn(make_float2(v0 - f01.x, v1 - f01.y));
        __nv_bfloat162 l23 = __float22bfloat162_rn(make_float2(v2 - f23.x, v3 - f23.y));
        *(__nv_bfloat162*)(outH + (size_t)pr * out_stride + col) = h01;
        *(__nv_bfloat162*)(outH + (size_t)(pr + 8) * out_stride + col) = h23;
        *(__nv_bfloat162*)(outL + (size_t)pr * out_stride + col) = l01;
        *(__nv_bfloat162*)(outL + (size_t)(pr + 8) * out_stride + col) = l23;
    }
}

// ---------------- launch ----------------
extern "C" void kernel_launch(void* const* d_in, const int* in_sizes, int n_in,
                              void* d_out, int out_size) {
    const float* x     = (const float*)d_in[0];
    const float* mu    = (const float*)d_in[1];
    const float* sigma = (const float*)d_in[2];
    const float* wf    = (const float*)d_in[3];
    const float* bfl   = (const float*)d_in[4];
    const float* m     = (const float*)d_in[5];
    const int*   perm  = (const int*)d_in[6];
    float* out = (float*)d_out;

    char *wp, *mp;
    float *Xa, *Xb;
    __nv_bfloat16 *XaH, *XaL, *XbH, *XbL, *T1H, *T1L, *T2H, *T2L;
    cudaGetSymbolAddress((void**)&wp, g_wpc);
    cudaGetSymbolAddress((void**)&mp, g_mpc);
    cudaGetSymbolAddress((void**)&Xa, g_Xa);
    cudaGetSymbolAddress((void**)&Xb, g_Xb);
    cudaGetSymbolAddress((void**)&XaH, g_XaH);
    cudaGetSymbolAddress((void**)&XaL, g_XaL);
    cudaGetSymbolAddress((void**)&XbH, g_XbH);
    cudaGetSymbolAddress((void**)&XbL, g_XbL);
    cudaGetSymbolAddress((void**)&T1H, g_T1H);
    cudaGetSymbolAddress((void**)&T1L, g_T1L);
    cudaGetSymbolAddress((void**)&T2H, g_T2H);
    cudaGetSymbolAddress((void**)&T2L, g_T2L);

    // dynamic smem: 480 * (32 + OC) bytes
    const int SM128 = 480 * (32 + 128);   // 76800
    const int SM96  = 480 * (32 + 96);    // 61440
    const int SM192 = 480 * (32 + 192);   // 107520
    static bool attr_done = false;
    if (!attr_done) {
        cudaFuncSetAttribute(k_mma<96, 128, 3, true, false>,  cudaFuncAttributeMaxDynamicSharedMemorySize, SM128);
        cudaFuncSetAttribute(k_mma<128, 128, 3, true, false>, cudaFuncAttributeMaxDynamicSharedMemorySize, SM128);
        cudaFuncSetAttribute(k_mma<128, 96, 3, false, true>,  cudaFuncAttributeMaxDynamicSharedMemorySize, SM96);
        cudaFuncSetAttribute(k_mma<192, 192, 1, false, false>, cudaFuncAttributeMaxDynamicSharedMemorySize, SM192);
        attr_done = true;
    }

    k_wp<<<(WTOT + 255) / 256, 256>>>(wf);
    k_mp<<<(32 * 36864 + 255) / 256, 256>>>(m);
    k_pre<<<(NP * 192 + 255) / 256, 256>>>(x, mu, sigma, perm, Xa, XaH, XaL);

    const size_t pre_j[6] = {0, 442368, 1032192, 1474560, 1916928, 2506752};
    const int bstart[6] = {0, 128, 256, 352, 480, 608};

    float* X = Xa;  __nv_bfloat16 *XH = XaH, *XL = XaL;
    float* Y = Xb;  __nv_bfloat16 *YH = XbH, *YL = XbL;
    for (int blk = 0; blk < 32; blk++) {
        const char* wb = wp + (size_t)blk * WP_PER_BLK;
        const float* bb = bfl + blk * 704;
        // round 0: x1 += f0(x2)
        k_mma<96, 128, 3, true, false><<<256, 256, SM128>>>(XH + 96, XL + 96, 192, wb + pre_j[0], bb + bstart[0], nullptr, 0, nullptr, T1H, T1L, 128);
        k_mma<128, 128, 3, true, false><<<256, 256, SM128>>>(T1H, T1L, 128, wb + pre_j[1], bb + bstart[1], nullptr, 0, nullptr, T2H, T2L, 128);
        k_mma<128, 96, 3, false, true><<<256, 256, SM96>>>(T2H, T2L, 128, wb + pre_j[2], bb + bstart[2], X + 0, 192, X + 0, XH + 0, XL + 0, 192);
        // round 1: x2 += f1(x1)
        k_mma<96, 128, 3, true, false><<<256, 256, SM128>>>(XH + 0, XL + 0, 192, wb + pre_j[3], bb + bstart[3], nullptr, 0, nullptr, T1H, T1L, 128);
        k_mma<128, 128, 3, true, false><<<256, 256, SM128>>>(T1H, T1L, 128, wb + pre_j[4], bb + bstart[4], nullptr, 0, nullptr, T2H, T2L, 128);
        k_mma<128, 96, 3, false, true><<<256, 256, SM96>>>(T2H, T2L, 128, wb + pre_j[5], bb + bstart[5], X + 96, 192, X + 96, XH + 96, XL + 96, 192);
        // 1x1 mixing
        k_mma<192, 192, 1, false, false><<<256, 256, SM192>>>(XH, XL, 192, mp + (size_t)blk * MP_PER_BLK, nullptr, nullptr, 0, Y, YH, YL, 192);
        float* tf = X; X = Y; Y = tf;
        __nv_bfloat16* th = XH; XH = YH; YH = th;
        __nv_bfloat16* tl = XL; XL = YL; YL = tl;
    }

    k_post<<<(NP * 192 + 255) / 256, 256>>>(X, out);
}

// round 8
// speedup vs baseline: 1.2135x; 1.2135x over previous
#include <cuda_runtime.h>
#include <cuda_bf16.h>
#include <cstdint>
#include <cstring>

// ---------------- constants ----------------
constexpr int NP = 8192;
constexpr int WTOT = 23592960;
constexpr int PER_BLK_W = 737280;
constexpr size_t WP_PER_BLK = 2949120;     // 4 bytes per weight (hi+lo bf16)
constexpr size_t MP_PER_BLK = 147456;

// ---------------- device scratch ----------------
__device__ char g_wpc[32 * WP_PER_BLK];
__device__ char g_mpc[32 * MP_PER_BLK];
__device__ float g_Xa[NP * 192], g_Xb[NP * 192];
__device__ __nv_bfloat16 g_XaH[NP * 192], g_XaL[NP * 192];
__device__ __nv_bfloat16 g_XbH[NP * 192], g_XbL[NP * 192];
__device__ __nv_bfloat16 g_T1H[NP * 128], g_T1L[NP * 128];
__device__ __nv_bfloat16 g_T2H[NP * 128], g_T2L[NP * 128];

// ---------------- helpers ----------------
__device__ __forceinline__ uint32_t smem_u32(const void* p) {
    uint32_t a;
    asm("{ .reg .u64 t; cvta.to.shared.u64 t, %1; cvt.u32.u64 %0, t; }" : "=r"(a) : "l"(p));
    return a;
}
__device__ __forceinline__ unsigned short f2bf(float v) {
    __nv_bfloat16 b = __float2bfloat16(v);
    unsigned short u; memcpy(&u, &b, 2);
    return u;
}
__device__ __forceinline__ float bf2f(unsigned short u) {
    __nv_bfloat16 b; memcpy(&b, &u, 2);
    return __bfloat162float(b);
}
__device__ __forceinline__ void ldm4(uint32_t* r, uint32_t addr) {
    asm volatile("ldmatrix.sync.aligned.m8n8.x4.shared.b16 {%0,%1,%2,%3}, [%4];"
        : "=r"(r[0]), "=r"(r[1]), "=r"(r[2]), "=r"(r[3]) : "r"(addr));
}
__device__ __forceinline__ void ldm2(uint32_t* r, uint32_t addr) {
    asm volatile("ldmatrix.sync.aligned.m8n8.x2.shared.b16 {%0,%1}, [%2];"
        : "=r"(r[0]), "=r"(r[1]) : "r"(addr));
}
__device__ __forceinline__ void mma16816(float* d, const uint32_t* a, uint32_t b0, uint32_t b1) {
    asm volatile("mma.sync.aligned.m16n8k16.row.col.f32.bf16.bf16.f32 "
        "{%0,%1,%2,%3},{%4,%5,%6,%7},{%8,%9},{%0,%1,%2,%3};"
        : "+f"(d[0]), "+f"(d[1]), "+f"(d[2]), "+f"(d[3])
        : "r"(a[0]), "r"(a[1]), "r"(a[2]), "r"(a[3]), "r"(b0), "r"(b1));
}
__device__ __forceinline__ void cpa16(uint32_t dst, const void* src, uint32_t srcsz) {
    asm volatile("cp.async.cg.shared.global [%0], [%1], 16, %2;"
        :: "r"(dst), "l"(src), "r"(srcsz) : "memory");
}
#define CP_COMMIT() asm volatile("cp.async.commit_group;" ::: "memory")
#define CP_WAIT0()  asm volatile("cp.async.wait_group 0;" ::: "memory")

// ---------------- weight prepack (convs) ----------------
// Per conv j, per tap: [hi OC x IC bf16][lo OC x IC bf16], dense rows.
__global__ void k_wp(const float* __restrict__ wf) {
    int idx = blockIdx.x * 256 + threadIdx.x;
    if (idx >= WTOT) return;
    int blk = idx / PER_BLK_W;
    int r = idx - blk * PER_BLK_W;
    const int starts[6] = {0, 110592, 258048, 368640, 479232, 626688};
    const size_t pre[6] = {0, 442368, 1032192, 1474560, 1916928, 2506752};
    int j = 0;
#pragma unroll
    for (int t = 1; t < 6; t++) if (r >= starts[t]) j = t;
    int off = r - starts[j];
    int oc = ((j % 3) == 2) ? 96 : 128;
    int ic = ((j % 3) == 0) ? 96 : 128;
    int o = off / (ic * 9);
    int rem = off - o * ic * 9;
    int c = rem / 9;
    int tap = rem - c * 9;
    float v = wf[idx];
    unsigned short hb = f2bf(v);
    unsigned short lb = f2bf(v - bf2f(hb));
    size_t base = (size_t)blk * WP_PER_BLK + pre[j] + (size_t)tap * (oc * ic * 4);
    size_t e = (size_t)(o * ic + c) * 2;
    *(unsigned short*)(g_wpc + base + e) = hb;
    *(unsigned short*)(g_wpc + base + (size_t)oc * ic * 2 + e) = lb;
}

// ---------------- mixing prepack: [hi 192x192][lo 192x192] ----------------
__global__ void k_mp(const float* __restrict__ m) {
    int idx = blockIdx.x * 256 + threadIdx.x;
    if (idx >= 32 * 36864) return;
    int blk = idx / 36864;
    int r = idx - blk * 36864;
    float v = m[idx];
    unsigned short hb = f2bf(v);
    unsigned short lb = f2bf(v - bf2f(hb));
    size_t base = (size_t)blk * MP_PER_BLK;
    *(unsigned short*)(g_mpc + base + (size_t)r * 2) = hb;
    *(unsigned short*)(g_mpc + base + 73728 + (size_t)r * 2) = lb;
}

// ---------------- normalize + permute + space_to_depth -> NHWC ----------------
__global__ void k_pre(const float* __restrict__ x, const float* __restrict__ mu,
                      const float* __restrict__ sigma, const int* __restrict__ perm,
                      float* __restrict__ Xo, __nv_bfloat16* __restrict__ XoH,
                      __nv_bfloat16* __restrict__ XoL) {
    int idx = blockIdx.x * 256 + threadIdx.x;
    if (idx >= NP * 192) return;
    int ch = idx % 192;
    int p = idx / 192;
    int w = p & 31, h = (p >> 5) & 31, b = p >> 10;
    int c = ch >> 6, r = ch & 63;
    int bi = r >> 3, bj = r & 7;
    int flat = (h * 8 + bi) * 256 + (w * 8 + bj);
    int src = perm[c * 65536 + flat];
    float v = (x[(b * 3 + c) * 65536 + src] - mu[c]) / sigma[c];
    Xo[idx] = v;
    unsigned short hb = f2bf(v);
    XoH[idx] = *(__nv_bfloat16*)&hb;
    unsigned short lb = f2bf(v - bf2f(hb));
    XoL[idx] = *(__nv_bfloat16*)&lb;
}

// ---------------- final NHWC -> NCHW ----------------
__global__ void k_post(const float* __restrict__ X, float* __restrict__ out) {
    int idx = blockIdx.x * 256 + threadIdx.x;
    if (idx >= NP * 192) return;
    int w = idx & 31;
    int h = (idx >> 5) & 31;
    int ch = (idx >> 10) % 192;
    int b = idx / (192 * 1024);
    out[idx] = X[(((b * 32 + h) * 32 + w) * 192) + ch];
}

// ---------------- warp-mma bf16x3 implicit-GEMM conv, tap-stage pipeline ----------------
// CTA = 64 positions x full OC, 8 warps (2M x 4N, warp 32x32).
// Stage = one tap, K = IC per stage. Double-buffered smem, 1 barrier/stage.
// Within a stage: IC/16 ksteps with register-fragment double buffering.
template <int IC, int OC, int KS, bool RELU, bool ADDIN>
__global__ __launch_bounds__(256, 1) void k_mma(
    const __nv_bfloat16* __restrict__ inH, const __nv_bfloat16* __restrict__ inL,
    int in_stride,
    const char* __restrict__ wp,
    const float* __restrict__ bias,
    const float* __restrict__ addp, int add_stride,
    float* __restrict__ out,
    __nv_bfloat16* __restrict__ outH, __nv_bfloat16* __restrict__ outL,
    int out_stride)
{
    constexpr int NST = KS * KS;
    constexpr int NBUF = (NST > 1) ? 2 : 1;
    constexpr int KST = IC / 16;         // k16 steps per stage
    constexpr int CPR = IC / 8;          // 16B chunks per row
    constexpr int LDK = IC + 8;          // padded row stride (b16 units)
    constexpr int NT = OC / 32;          // n8 tiles per warp
    constexpr int NP2 = NT / 2;          // full ldm4 B pairs
    constexpr int TAIL = NT & 1;
    constexpr int ASZ = 64 * LDK;        // b16 per A plane buffer
    constexpr int BSZ = OC * LDK;
    constexpr int PH = KS / 2;
    constexpr int LDKb = LDK * 2;

    extern __shared__ __align__(16) unsigned short smem[];
    unsigned short* Ah = smem;
    unsigned short* Al = Ah + NBUF * ASZ;
    unsigned short* Bh = Al + NBUF * ASZ;
    unsigned short* Bl = Bh + NBUF * BSZ;

    const int tid = threadIdx.x;
    const int wid = tid >> 5, lane = tid & 31;
    const int wm = wid & 1, wn = wid >> 1;
    const int p0 = blockIdx.x * 64;
    const int b = p0 >> 10;
    const int h0 = (p0 >> 5) & 31;       // tile covers image rows h0, h0+1

    float acc[2][NT][4];
#pragma unroll
    for (int i = 0; i < 2; i++)
#pragma unroll
        for (int j = 0; j < NT; j++)
#pragma unroll
            for (int q = 0; q < 4; q++) acc[i][j][q] = 0.f;

    const uint32_t sAh = smem_u32(Ah), sAl = smem_u32(Al);
    const uint32_t sBh = smem_u32(Bh), sBl = smem_u32(Bl);

    auto issue = [&](int s, int buf) {
        const int ky = s / KS - PH, kx = s - (s / KS) * KS - PH;
#pragma unroll
        for (int i = tid; i < 64 * CPR; i += 256) {
            int row = i / CPR, ck = i - row * CPR;
            int hh = h0 + (row >> 5) + ky, ww = (row & 31) + kx;
            bool ok = (hh >= 0) && (hh < 32) && (ww >= 0) && (ww < 32);
            size_t aoff = ok ? ((size_t)(((b << 5) + hh) * 32 + ww) * in_stride + ck * 8) : 0;
            uint32_t sz = ok ? 16u : 0u;
            uint32_t d = (uint32_t)(buf * ASZ + row * LDK + ck * 8) * 2;
            cpa16(sAh + d, inH + aoff, sz);
            cpa16(sAl + d, inL + aoff, sz);
        }
        const char* bu = wp + (size_t)s * (OC * IC * 4);
#pragma unroll
        for (int i = tid; i < OC * CPR; i += 256) {
            int rr = i / CPR, ck = i - rr * CPR;
            size_t so = (size_t)(rr * IC + ck * 8) * 2;
            uint32_t d = (uint32_t)(buf * BSZ + rr * LDK + ck * 8) * 2;
            cpa16(sBh + d, bu + so, 16);
            cpa16(sBl + d, bu + (size_t)OC * IC * 2 + so, 16);
        }
        CP_COMMIT();
    };

    issue(0, 0);

    for (int s = 0; s < NST; s++) {
        CP_WAIT0();
        __syncthreads();
        if (s + 1 < NST) issue(s + 1, (s + 1) & 1);

        const int cb = s & (NBUF - 1);
        const uint32_t aAh = sAh + (uint32_t)(cb * ASZ) * 2;
        const uint32_t aAl = sAl + (uint32_t)(cb * ASZ) * 2;
        const uint32_t aBh = sBh + (uint32_t)(cb * BSZ) * 2;
        const uint32_t aBl = sBl + (uint32_t)(cb * BSZ) * 2;

        // register fragments, double-buffered over ksteps
        uint32_t fah[2][2][4], fal[2][2][4];
        uint32_t fbh[2][NP2 ? NP2 : 1][4], fbl[2][NP2 ? NP2 : 1][4];
        uint32_t fth[2][2], ftl[2][2];

        auto ldfrag = [&](int ks, int fb) {
#pragma unroll
            for (int mt = 0; mt < 2; mt++) {
                uint32_t ro = (uint32_t)(wm * 32 + mt * 16 + (lane & 15)) * LDKb
                            + (uint32_t)ks * 32 + ((lane >> 4) * 16);
                ldm4(fah[fb][mt], aAh + ro);
                ldm4(fal[fb][mt], aAl + ro);
            }
#pragma unroll
            for (int p = 0; p < NP2; p++) {
                uint32_t ro = (uint32_t)(wn * (OC / 4) + p * 16 + (lane & 15)) * LDKb
                            + (uint32_t)ks * 32 + ((lane >> 4) * 16);
                ldm4(fbh[fb][p], aBh + ro);
                ldm4(fbl[fb][p], aBl + ro);
            }
            if (TAIL) {
                uint32_t ro = (uint32_t)(wn * (OC / 4) + NP2 * 16 + (lane & 7)) * LDKb
                            + (uint32_t)ks * 32 + (((lane >> 3) & 1) * 16);
                ldm2(fth[fb], aBh + ro);
                ldm2(ftl[fb], aBl + ro);
            }
        };

        ldfrag(0, 0);
#pragma unroll
        for (int ks = 0; ks < KST; ks++) {
            if (ks + 1 < KST) ldfrag(ks + 1, (ks + 1) & 1);
            const int fb = ks & 1;
#pragma unroll
            for (int p = 0; p < NP2; p++) {
#pragma unroll
                for (int sub = 0; sub < 2; sub++) {
#pragma unroll
                    for (int mt = 0; mt < 2; mt++) {
                        float* d = acc[mt][p * 2 + sub];
                        mma16816(d, fah[fb][mt], fbh[fb][p][sub], fbh[fb][p][sub + 2]);
                        mma16816(d, fah[fb][mt], fbl[fb][p][sub], fbl[fb][p][sub + 2]);
                        mma16816(d, fal[fb][mt], fbh[fb][p][sub], fbh[fb][p][sub + 2]);
                    }
                }
            }
            if (TAIL) {
#pragma unroll
                for (int mt = 0; mt < 2; mt++) {
                    float* d = acc[mt][NT - 1];
                    mma16816(d, fah[fb][mt], fth[fb][0], fth[fb][1]);
                    mma16816(d, fah[fb][mt], ftl[fb][0], ftl[fb][1]);
                    mma16816(d, fal[fb][mt], fth[fb][0], fth[fb][1]);
                }
            }
        }
    }

    // ---- epilogue ----
    const int l4 = lane >> 2, l2 = (lane & 3) * 2;
#pragma unroll
    for (int nt = 0; nt < NT; nt++) {
        const int col = wn * (OC / 4) + nt * 8 + l2;
        float b0 = 0.f, b1 = 0.f;
        if (bias) { b0 = bias[col]; b1 = bias[col + 1]; }
#pragma unroll
        for (int mt = 0; mt < 2; mt++) {
            const int pr = p0 + wm * 32 + mt * 16 + l4;
            float* d = acc[mt][nt];
            float v0 = d[0] + b0, v1 = d[1] + b1, v2 = d[2] + b0, v3 = d[3] + b1;
            if (RELU) {
                v0 = fmaxf(v0, 0.f); v1 = fmaxf(v1, 0.f);
                v2 = fmaxf(v2, 0.f); v3 = fmaxf(v3, 0.f);
            }
            if (ADDIN) {
                float2 a0 = *(const float2*)(addp + (size_t)pr * add_stride + col);
                float2 a1 = *(const float2*)(addp + (size_t)(pr + 8) * add_stride + col);
                v0 += a0.x; v1 += a0.y; v2 += a1.x; v3 += a1.y;
            }
            if (out) {
                *(float2*)(out + (size_t)pr * out_stride + col) = make_float2(v0, v1);
                *(float2*)(out + (size_t)(pr + 8) * out_stride + col) = make_float2(v2, v3);
            }
            __nv_bfloat162 h01 = __float22bfloat162_rn(make_float2(v0, v1));
            __nv_bfloat162 h23 = __float22bfloat162_rn(make_float2(v2, v3));
            float2 f01 = __bfloat1622float2(h01);
            float2 f23 = __bfloat1622float2(h23);
            __nv_bfloat162 l01 = __float22bfloat162_rn(make_float2(v0 - f01.x, v1 - f01.y));
            __nv_bfloat162 l23 = __float22bfloat162_rn(make_float2(v2 - f23.x, v3 - f23.y));
            *(__nv_bfloat162*)(outH + (size_t)pr * out_stride + col) = h01;
            *(__nv_bfloat162*)(outH + (size_t)(pr + 8) * out_stride + col) = h23;
            *(__nv_bfloat162*)(outL + (size_t)pr * out_stride + col) = l01;
            *(__nv_bfloat162*)(outL + (size_t)(pr + 8) * out_stride + col) = l23;
        }
    }
}

// ---------------- launch ----------------
extern "C" void kernel_launch(void* const* d_in, const int* in_sizes, int n_in,
                              void* d_out, int out_size) {
    const float* x     = (const float*)d_in[0];
    const float* mu    = (const float*)d_in[1];
    const float* sigma = (const float*)d_in[2];
    const float* wf    = (const float*)d_in[3];
    const float* bfl   = (const float*)d_in[4];
    const float* m     = (const float*)d_in[5];
    const int*   perm  = (const int*)d_in[6];
    float* out = (float*)d_out;

    char *wp, *mp;
    float *Xa, *Xb;
    __nv_bfloat16 *XaH, *XaL, *XbH, *XbL, *T1H, *T1L, *T2H, *T2L;
    cudaGetSymbolAddress((void**)&wp, g_wpc);
    cudaGetSymbolAddress((void**)&mp, g_mpc);
    cudaGetSymbolAddress((void**)&Xa, g_Xa);
    cudaGetSymbolAddress((void**)&Xb, g_Xb);
    cudaGetSymbolAddress((void**)&XaH, g_XaH);
    cudaGetSymbolAddress((void**)&XaL, g_XaL);
    cudaGetSymbolAddress((void**)&XbH, g_XbH);
    cudaGetSymbolAddress((void**)&XbL, g_XbL);
    cudaGetSymbolAddress((void**)&T1H, g_T1H);
    cudaGetSymbolAddress((void**)&T1L, g_T1L);
    cudaGetSymbolAddress((void**)&T2H, g_T2H);
    cudaGetSymbolAddress((void**)&T2L, g_T2L);

    // dynamic smem bytes: NBUF * 4 * LDK * (64 + OC)
    const int SM_C1 = 2 * 4 * 104 * (64 + 128);   // 159744
    const int SM_C2 = 2 * 4 * 136 * (64 + 128);   // 208896
    const int SM_C3 = 2 * 4 * 136 * (64 + 96);    // 174080
    const int SM_MX = 1 * 4 * 200 * (64 + 192);   // 204800
    static bool attr_done = false;
    if (!attr_done) {
        cudaFuncSetAttribute(k_mma<96, 128, 3, true, false>,  cudaFuncAttributeMaxDynamicSharedMemorySize, SM_C1);
        cudaFuncSetAttribute(k_mma<128, 128, 3, true, false>, cudaFuncAttributeMaxDynamicSharedMemorySize, SM_C2);
        cudaFuncSetAttribute(k_mma<128, 96, 3, false, true>,  cudaFuncAttributeMaxDynamicSharedMemorySize, SM_C3);
        cudaFuncSetAttribute(k_mma<192, 192, 1, false, false>, cudaFuncAttributeMaxDynamicSharedMemorySize, SM_MX);
        attr_done = true;
    }

    k_wp<<<(WTOT + 255) / 256, 256>>>(wf);
    k_mp<<<(32 * 36864 + 255) / 256, 256>>>(m);
    k_pre<<<(NP * 192 + 255) / 256, 256>>>(x, mu, sigma, perm, Xa, XaH, XaL);

    const size_t pre_j[6] = {0, 442368, 1032192, 1474560, 1916928, 2506752};
    const int bstart[6] = {0, 128, 256, 352, 480, 608};

    float* X = Xa;  __nv_bfloat16 *XH = XaH, *XL = XaL;
    float* Y = Xb;  __nv_bfloat16 *YH = XbH, *YL = XbL;
    for (int blk = 0; blk < 32; blk++) {
        const char* wb = wp + (size_t)blk * WP_PER_BLK;
        const float* bb = bfl + blk * 704;
        // round 0: x1 += f0(x2)
        k_mma<96, 128, 3, true, false><<<128, 256, SM_C1>>>(XH + 96, XL + 96, 192, wb + pre_j[0], bb + bstart[0], nullptr, 0, nullptr, T1H, T1L, 128);
        k_mma<128, 128, 3, true, false><<<128, 256, SM_C2>>>(T1H, T1L, 128, wb + pre_j[1], bb + bstart[1], nullptr, 0, nullptr, T2H, T2L, 128);
        k_mma<128, 96, 3, false, true><<<128, 256, SM_C3>>>(T2H, T2L, 128, wb + pre_j[2], bb + bstart[2], X + 0, 192, X + 0, XH + 0, XL + 0, 192);
        // round 1: x2 += f1(x1)
        k_mma<96, 128, 3, true, false><<<128, 256, SM_C1>>>(XH + 0, XL + 0, 192, wb + pre_j[3], bb + bstart[3], nullptr, 0, nullptr, T1H, T1L, 128);
        k_mma<128, 128, 3, true, false><<<128, 256, SM_C2>>>(T1H, T1L, 128, wb + pre_j[4], bb + bstart[4], nullptr, 0, nullptr, T2H, T2L, 128);
        k_mma<128, 96, 3, false, true><<<128, 256, SM_C3>>>(T2H, T2L, 128, wb + pre_j[5], bb + bstart[5], X + 96, 192, X + 96, XH + 96, XL + 96, 192);
        // 1x1 mixing
        k_mma<192, 192, 1, false, false><<<128, 256, SM_MX>>>(XH, XL, 192, mp + (size_t)blk * MP_PER_BLK, nullptr, nullptr, 0, Y, YH, YL, 192);
        float* tf = X; X = Y; Y = tf;
        __nv_bfloat16* th = XH; XH = YH; YH = th;
        __nv_bfloat16* tl = XL; XL = YL; YL = tl;
    }

    k_post<<<(NP * 192 + 255) / 256, 256>>>(X, out);
}

// round 9
// speedup vs baseline: 1.3242x; 1.0912x over previous
#include <cuda_runtime.h>
#include <cuda_bf16.h>
#include <cstdint>
#include <cstring>

// ---------------- constants ----------------
constexpr int NP = 8192;
constexpr int WTOT = 23592960;
constexpr int PER_BLK_W = 737280;
constexpr size_t WP_PER_BLK = 2949120;     // 4 bytes per weight (hi+lo bf16)
constexpr size_t MP_PER_BLK = 147456;

// ---------------- device scratch ----------------
__device__ char g_wpc[32 * WP_PER_BLK];
__device__ char g_mpc[32 * MP_PER_BLK];
__device__ float g_Xa[NP * 192], g_Xb[NP * 192];
__device__ __nv_bfloat16 g_XaH[NP * 192], g_XaL[NP * 192];
__device__ __nv_bfloat16 g_XbH[NP * 192], g_XbL[NP * 192];
__device__ __nv_bfloat16 g_T1H[NP * 128], g_T1L[NP * 128];
__device__ __nv_bfloat16 g_T2H[NP * 128], g_T2L[NP * 128];

// ---------------- helpers ----------------
__device__ __forceinline__ uint32_t smem_u32(const void* p) {
    uint32_t a;
    asm("{ .reg .u64 t; cvta.to.shared.u64 t, %1; cvt.u32.u64 %0, t; }" : "=r"(a) : "l"(p));
    return a;
}
__device__ __forceinline__ unsigned short f2bf(float v) {
    __nv_bfloat16 b = __float2bfloat16(v);
    unsigned short u; memcpy(&u, &b, 2);
    return u;
}
__device__ __forceinline__ float bf2f(unsigned short u) {
    __nv_bfloat16 b; memcpy(&b, &u, 2);
    return __bfloat162float(b);
}
__device__ __forceinline__ void ldm4(uint32_t* r, uint32_t addr) {
    asm volatile("ldmatrix.sync.aligned.m8n8.x4.shared.b16 {%0,%1,%2,%3}, [%4];"
        : "=r"(r[0]), "=r"(r[1]), "=r"(r[2]), "=r"(r[3]) : "r"(addr));
}
__device__ __forceinline__ void ldm2(uint32_t* r, uint32_t addr) {
    asm volatile("ldmatrix.sync.aligned.m8n8.x2.shared.b16 {%0,%1}, [%2];"
        : "=r"(r[0]), "=r"(r[1]) : "r"(addr));
}
__device__ __forceinline__ void mma16816(float* d, const uint32_t* a, uint32_t b0, uint32_t b1) {
    asm volatile("mma.sync.aligned.m16n8k16.row.col.f32.bf16.bf16.f32 "
        "{%0,%1,%2,%3},{%4,%5,%6,%7},{%8,%9},{%0,%1,%2,%3};"
        : "+f"(d[0]), "+f"(d[1]), "+f"(d[2]), "+f"(d[3])
        : "r"(a[0]), "r"(a[1]), "r"(a[2]), "r"(a[3]), "r"(b0), "r"(b1));
}
__device__ __forceinline__ void cpa16(uint32_t dst, const void* src, uint32_t srcsz) {
    asm volatile("cp.async.cg.shared.global [%0], [%1], 16, %2;"
        :: "r"(dst), "l"(src), "r"(srcsz) : "memory");
}
#define CP_COMMIT() asm volatile("cp.async.commit_group;" ::: "memory")
#define CP_WAIT0()  asm volatile("cp.async.wait_group 0;" ::: "memory")

// ---------------- weight prepack (convs) ----------------
// Per conv j, per tap: [hi OC x IC bf16][lo OC x IC bf16], dense rows.
__global__ void k_wp(const float* __restrict__ wf) {
    int idx = blockIdx.x * 256 + threadIdx.x;
    if (idx >= WTOT) return;
    int blk = idx / PER_BLK_W;
    int r = idx - blk * PER_BLK_W;
    const int starts[6] = {0, 110592, 258048, 368640, 479232, 626688};
    const size_t pre[6] = {0, 442368, 1032192, 1474560, 1916928, 2506752};
    int j = 0;
#pragma unroll
    for (int t = 1; t < 6; t++) if (r >= starts[t]) j = t;
    int off = r - starts[j];
    int oc = ((j % 3) == 2) ? 96 : 128;
    int ic = ((j % 3) == 0) ? 96 : 128;
    int o = off / (ic * 9);
    int rem = off - o * ic * 9;
    int c = rem / 9;
    int tap = rem - c * 9;
    float v = wf[idx];
    unsigned short hb = f2bf(v);
    unsigned short lb = f2bf(v - bf2f(hb));
    size_t base = (size_t)blk * WP_PER_BLK + pre[j] + (size_t)tap * (oc * ic * 4);
    size_t e = (size_t)(o * ic + c) * 2;
    *(unsigned short*)(g_wpc + base + e) = hb;
    *(unsigned short*)(g_wpc + base + (size_t)oc * ic * 2 + e) = lb;
}

// ---------------- mixing prepack: [hi 192x192][lo 192x192] ----------------
__global__ void k_mp(const float* __restrict__ m) {
    int idx = blockIdx.x * 256 + threadIdx.x;
    if (idx >= 32 * 36864) return;
    int blk = idx / 36864;
    int r = idx - blk * 36864;
    float v = m[idx];
    unsigned short hb = f2bf(v);
    unsigned short lb = f2bf(v - bf2f(hb));
    size_t base = (size_t)blk * MP_PER_BLK;
    *(unsigned short*)(g_mpc + base + (size_t)r * 2) = hb;
    *(unsigned short*)(g_mpc + base + 73728 + (size_t)r * 2) = lb;
}

// ---------------- normalize + permute + space_to_depth -> NHWC ----------------
__global__ void k_pre(const float* __restrict__ x, const float* __restrict__ mu,
                      const float* __restrict__ sigma, const int* __restrict__ perm,
                      float* __restrict__ Xo, __nv_bfloat16* __restrict__ XoH,
                      __nv_bfloat16* __restrict__ XoL) {
    int idx = blockIdx.x * 256 + threadIdx.x;
    if (idx >= NP * 192) return;
    int ch = idx % 192;
    int p = idx / 192;
    int w = p & 31, h = (p >> 5) & 31, b = p >> 10;
    int c = ch >> 6, r = ch & 63;
    int bi = r >> 3, bj = r & 7;
    int flat = (h * 8 + bi) * 256 + (w * 8 + bj);
    int src = perm[c * 65536 + flat];
    float v = (x[(b * 3 + c) * 65536 + src] - mu[c]) / sigma[c];
    Xo[idx] = v;
    unsigned short hb = f2bf(v);
    XoH[idx] = *(__nv_bfloat16*)&hb;
    unsigned short lb = f2bf(v - bf2f(hb));
    XoL[idx] = *(__nv_bfloat16*)&lb;
}

// ---------------- final NHWC -> NCHW ----------------
__global__ void k_post(const float* __restrict__ X, float* __restrict__ out) {
    int idx = blockIdx.x * 256 + threadIdx.x;
    if (idx >= NP * 192) return;
    int w = idx & 31;
    int h = (idx >> 5) & 31;
    int ch = (idx >> 10) % 192;
    int b = idx / (192 * 1024);
    out[idx] = X[(((b * 32 + h) * 32 + w) * 192) + ch];
}

// ---------------- warp-mma bf16x3 implicit-GEMM conv, halo-A + tap stages ----------------
// CTA = 64 positions x full OC, 8 warps (2M x 4N, warp 32x32).
// A (hi+lo) loaded ONCE into a halo tile [(2+2PH) x (32+2PH)][IC]; per-tap
// fragments via ldmatrix per-lane row addressing. Per stage only B is copied
// (double buffered). Register-fragment double buffering over ksteps.
template <int IC, int OC, int KS, bool RELU, bool ADDIN>
__global__ __launch_bounds__(256, 1) void k_mma(
    const __nv_bfloat16* __restrict__ inH, const __nv_bfloat16* __restrict__ inL,
    int in_stride,
    const char* __restrict__ wp,
    const float* __restrict__ bias,
    const float* __restrict__ addp, int add_stride,
    float* __restrict__ out,
    __nv_bfloat16* __restrict__ outH, __nv_bfloat16* __restrict__ outL,
    int out_stride)
{
    constexpr int PH = KS / 2;
    constexpr int HR = 2 + 2 * PH;       // halo rows
    constexpr int HC = 32 + 2 * PH;      // halo cols
    constexpr int NPOS = HR * HC;
    constexpr int NST = KS * KS;
    constexpr int NBUF = (NST > 1) ? 2 : 1;
    constexpr int KST = IC / 16;
    constexpr int CPR = IC / 8;
    constexpr int LDC = IC + 8;          // padded channel stride (b16 units)
    constexpr int LDCb = LDC * 2;
    constexpr int NT = OC / 32;
    constexpr int NP2 = NT / 2;
    constexpr int TAIL = NT & 1;
    constexpr int ASZ = NPOS * LDC;      // b16 per A plane
    constexpr int BSZ = OC * LDC;        // b16 per B plane buffer

    extern __shared__ __align__(16) unsigned short smem[];
    unsigned short* Ah = smem;
    unsigned short* Al = Ah + ASZ;
    unsigned short* Bh = Al + ASZ;
    unsigned short* Bl = Bh + NBUF * BSZ;

    const int tid = threadIdx.x;
    const int wid = tid >> 5, lane = tid & 31;
    const int wm = wid & 1, wn = wid >> 1;
    const int p0 = blockIdx.x * 64;
    const int b = p0 >> 10;
    const int h0 = (p0 >> 5) & 31;

    float acc[2][NT][4];
#pragma unroll
    for (int i = 0; i < 2; i++)
#pragma unroll
        for (int j = 0; j < NT; j++)
#pragma unroll
            for (int q = 0; q < 4; q++) acc[i][j][q] = 0.f;

    const uint32_t sAh = smem_u32(Ah), sAl = smem_u32(Al);
    const uint32_t sBh = smem_u32(Bh), sBl = smem_u32(Bl);

    // A fragment per-lane halo pixel offsets (bytes), one per mt
    uint32_t apix[2];
#pragma unroll
    for (int mt = 0; mt < 2; mt++) {
        int p = wm * 32 + mt * 16 + (lane & 15);
        apix[mt] = (uint32_t)(((p >> 5) * HC + (p & 31)) * LDCb) + ((lane >> 4) * 16);
    }

    // ---- prologue: A halo copy (once) ----
    {
#pragma unroll 4
        for (int i = tid; i < NPOS * CPR; i += 256) {
            int pos = i / CPR, ck = i - pos * CPR;
            int hr = pos / HC, hc = pos - hr * HC;
            int hh = h0 + hr - PH, ww = hc - PH;
            bool ok = (hh >= 0) && (hh < 32) && (ww >= 0) && (ww < 32);
            size_t off = ok ? ((size_t)(((b << 5) + hh) * 32 + ww) * in_stride + ck * 8) : 0;
            uint32_t sz = ok ? 16u : 0u;
            uint32_t d = (uint32_t)(pos * LDC + ck * 8) * 2;
            cpa16(sAh + d, inH + off, sz);
            cpa16(sAl + d, inL + off, sz);
        }
    }

    auto issueB = [&](int s, int buf) {
        const char* bu = wp + (size_t)s * (OC * IC * 4);
#pragma unroll
        for (int i = tid; i < OC * CPR; i += 256) {
            int rr = i / CPR, ck = i - rr * CPR;
            size_t so = (size_t)(rr * IC + ck * 8) * 2;
            uint32_t d = (uint32_t)(buf * BSZ + rr * LDC + ck * 8) * 2;
            cpa16(sBh + d, bu + so, 16);
            cpa16(sBl + d, bu + (size_t)OC * IC * 2 + so, 16);
        }
        CP_COMMIT();
    };

    issueB(0, 0);   // commits A + B0 together

    for (int s = 0; s < NST; s++) {
        CP_WAIT0();
        __syncthreads();
        if (s + 1 < NST) issueB(s + 1, (s + 1) & 1);

        const uint32_t hoffb = (uint32_t)(((s / KS) * HC + (s - (s / KS) * KS)) * LDCb);
        const uint32_t aAh = sAh + hoffb;
        const uint32_t aAl = sAl + hoffb;
        const uint32_t aBh = sBh + (uint32_t)((s & (NBUF - 1)) * BSZ) * 2;
        const uint32_t aBl = sBl + (uint32_t)((s & (NBUF - 1)) * BSZ) * 2;

        uint32_t fah[2][2][4], fal[2][2][4];
        uint32_t fbh[2][NP2 ? NP2 : 1][4], fbl[2][NP2 ? NP2 : 1][4];
        uint32_t fth[2][2], ftl[2][2];

        auto ldfrag = [&](int ks, int fb) {
#pragma unroll
            for (int mt = 0; mt < 2; mt++) {
                uint32_t ro = apix[mt] + (uint32_t)ks * 32;
                ldm4(fah[fb][mt], aAh + ro);
                ldm4(fal[fb][mt], aAl + ro);
            }
#pragma unroll
            for (int p = 0; p < NP2; p++) {
                uint32_t ro = (uint32_t)(wn * (OC / 4) + p * 16 + (lane & 15)) * LDCb
                            + (uint32_t)ks * 32 + ((lane >> 4) * 16);
                ldm4(fbh[fb][p], aBh + ro);
                ldm4(fbl[fb][p], aBl + ro);
            }
            if (TAIL) {
                uint32_t ro = (uint32_t)(wn * (OC / 4) + NP2 * 16 + (lane & 7)) * LDCb
                            + (uint32_t)ks * 32 + (((lane >> 3) & 1) * 16);
                ldm2(fth[fb], aBh + ro);
                ldm2(ftl[fb], aBl + ro);
            }
        };

        ldfrag(0, 0);
#pragma unroll
        for (int ks = 0; ks < KST; ks++) {
            if (ks + 1 < KST) ldfrag(ks + 1, (ks + 1) & 1);
            const int fb = ks & 1;
#pragma unroll
            for (int p = 0; p < NP2; p++) {
#pragma unroll
                for (int sub = 0; sub < 2; sub++) {
#pragma unroll
                    for (int mt = 0; mt < 2; mt++) {
                        float* d = acc[mt][p * 2 + sub];
                        mma16816(d, fah[fb][mt], fbh[fb][p][sub], fbh[fb][p][sub + 2]);
                        mma16816(d, fah[fb][mt], fbl[fb][p][sub], fbl[fb][p][sub + 2]);
                        mma16816(d, fal[fb][mt], fbh[fb][p][sub], fbh[fb][p][sub + 2]);
                    }
                }
            }
            if (TAIL) {
#pragma unroll
                for (int mt = 0; mt < 2; mt++) {
                    float* d = acc[mt][NT - 1];
                    mma16816(d, fah[fb][mt], fth[fb][0], fth[fb][1]);
                    mma16816(d, fah[fb][mt], ftl[fb][0], ftl[fb][1]);
                    mma16816(d, fal[fb][mt], fth[fb][0], fth[fb][1]);
                }
            }
        }
    }

    // ---- epilogue ----
    const int l4 = lane >> 2, l2 = (lane & 3) * 2;
#pragma unroll
    for (int nt = 0; nt < NT; nt++) {
        const int col = wn * (OC / 4) + nt * 8 + l2;
        float b0 = 0.f, b1 = 0.f;
        if (bias) { b0 = bias[col]; b1 = bias[col + 1]; }
#pragma unroll
        for (int mt = 0; mt < 2; mt++) {
            const int pr = p0 + wm * 32 + mt * 16 + l4;
            float* d = acc[mt][nt];
            float v0 = d[0] + b0, v1 = d[1] + b1, v2 = d[2] + b0, v3 = d[3] + b1;
            if (RELU) {
                v0 = fmaxf(v0, 0.f); v1 = fmaxf(v1, 0.f);
                v2 = fmaxf(v2, 0.f); v3 = fmaxf(v3, 0.f);
            }
            if (ADDIN) {
                float2 a0 = *(const float2*)(addp + (size_t)pr * add_stride + col);
                float2 a1 = *(const float2*)(addp + (size_t)(pr + 8) * add_stride + col);
                v0 += a0.x; v1 += a0.y; v2 += a1.x; v3 += a1.y;
            }
            if (out) {
                *(float2*)(out + (size_t)pr * out_stride + col) = make_float2(v0, v1);
                *(float2*)(out + (size_t)(pr + 8) * out_stride + col) = make_float2(v2, v3);
            }
            __nv_bfloat162 h01 = __float22bfloat162_rn(make_float2(v0, v1));
            __nv_bfloat162 h23 = __float22bfloat162_rn(make_float2(v2, v3));
            float2 f01 = __bfloat1622float2(h01);
            float2 f23 = __bfloat1622float2(h23);
            __nv_bfloat162 l01 = __float22bfloat162_rn(make_float2(v0 - f01.x, v1 - f01.y));
            __nv_bfloat162 l23 = __float22bfloat162_rn(make_float2(v2 - f23.x, v3 - f23.y));
            *(__nv_bfloat162*)(outH + (size_t)pr * out_stride + col) = h01;
            *(__nv_bfloat162*)(outH + (size_t)(pr + 8) * out_stride + col) = h23;
            *(__nv_bfloat162*)(outL + (size_t)pr * out_stride + col) = l01;
            *(__nv_bfloat162*)(outL + (size_t)(pr + 8) * out_stride + col) = l23;
        }
    }
}

// ---------------- launch ----------------
extern "C" void kernel_launch(void* const* d_in, const int* in_sizes, int n_in,
                              void* d_out, int out_size) {
    const float* x     = (const float*)d_in[0];
    const float* mu    = (const float*)d_in[1];
    const float* sigma = (const float*)d_in[2];
    const float* wf    = (const float*)d_in[3];
    const float* bfl   = (const float*)d_in[4];
    const float* m     = (const float*)d_in[5];
    const int*   perm  = (const int*)d_in[6];
    float* out = (float*)d_out;

    char *wp, *mp;
    float *Xa, *Xb;
    __nv_bfloat16 *XaH, *XaL, *XbH, *XbL, *T1H, *T1L, *T2H, *T2L;
    cudaGetSymbolAddress((void**)&wp, g_wpc);
    cudaGetSymbolAddress((void**)&mp, g_mpc);
    cudaGetSymbolAddress((void**)&Xa, g_Xa);
    cudaGetSymbolAddress((void**)&Xb, g_Xb);
    cudaGetSymbolAddress((void**)&XaH, g_XaH);
    cudaGetSymbolAddress((void**)&XaL, g_XaL);
    cudaGetSymbolAddress((void**)&XbH, g_XbH);
    cudaGetSymbolAddress((void**)&XbL, g_XbL);
    cudaGetSymbolAddress((void**)&T1H, g_T1H);
    cudaGetSymbolAddress((void**)&T1L, g_T1L);
    cudaGetSymbolAddress((void**)&T2H, g_T2H);
    cudaGetSymbolAddress((void**)&T2L, g_T2L);

    // dynamic smem bytes: 4*(NPOS*LDC) + NBUF*4*(OC*LDC)
    const int SM_C1 = 4 * (136 * 104) + 2 * 4 * (128 * 104);   // 163,072
    const int SM_C2 = 4 * (136 * 136) + 2 * 4 * (128 * 136);   // 213,248
    const int SM_C3 = 4 * (136 * 136) + 2 * 4 * (96 * 136);    // 178,432
    const int SM_MX = 4 * (64 * 200) + 1 * 4 * (192 * 200);    // 204,800
    static bool attr_done = false;
    if (!attr_done) {
        cudaFuncSetAttribute(k_mma<96, 128, 3, true, false>,  cudaFuncAttributeMaxDynamicSharedMemorySize, SM_C1);
        cudaFuncSetAttribute(k_mma<128, 128, 3, true, false>, cudaFuncAttributeMaxDynamicSharedMemorySize, SM_C2);
        cudaFuncSetAttribute(k_mma<128, 96, 3, false, true>,  cudaFuncAttributeMaxDynamicSharedMemorySize, SM_C3);
        cudaFuncSetAttribute(k_mma<192, 192, 1, false, false>, cudaFuncAttributeMaxDynamicSharedMemorySize, SM_MX);
        attr_done = true;
    }

    k_wp<<<(WTOT + 255) / 256, 256>>>(wf);
    k_mp<<<(32 * 36864 + 255) / 256, 256>>>(m);
    k_pre<<<(NP * 192 + 255) / 256, 256>>>(x, mu, sigma, perm, Xa, XaH, XaL);

    const size_t pre_j[6] = {0, 442368, 1032192, 1474560, 1916928, 2506752};
    const int bstart[6] = {0, 128, 256, 352, 480, 608};

    float* X = Xa;  __nv_bfloat16 *XH = XaH, *XL = XaL;
    float* Y = Xb;  __nv_bfloat16 *YH = XbH, *YL = XbL;
    for (int blk = 0; blk < 32; blk++) {
        const char* wb = wp + (size_t)blk * WP_PER_BLK;
        const float* bb = bfl + blk * 704;
        // round 0: x1 += f0(x2)
        k_mma<96, 128, 3, true, false><<<128, 256, SM_C1>>>(XH + 96, XL + 96, 192, wb + pre_j[0], bb + bstart[0], nullptr, 0, nullptr, T1H, T1L, 128);
        k_mma<128, 128, 3, true, false><<<128, 256, SM_C2>>>(T1H, T1L, 128, wb + pre_j[1], bb + bstart[1], nullptr, 0, nullptr, T2H, T2L, 128);
        k_mma<128, 96, 3, false, true><<<128, 256, SM_C3>>>(T2H, T2L, 128, wb + pre_j[2], bb + bstart[2], X + 0, 192, X + 0, XH + 0, XL + 0, 192);
        // round 1: x2 += f1(x1)
        k_mma<96, 128, 3, true, false><<<128, 256, SM_C1>>>(XH + 0, XL + 0, 192, wb + pre_j[3], bb + bstart[3], nullptr, 0, nullptr, T1H, T1L, 128);
        k_mma<128, 128, 3, true, false><<<128, 256, SM_C2>>>(T1H, T1L, 128, wb + pre_j[4], bb + bstart[4], nullptr, 0, nullptr, T2H, T2L, 128);
        k_mma<128, 96, 3, false, true><<<128, 256, SM_C3>>>(T2H, T2L, 128, wb + pre_j[5], bb + bstart[5], X + 96, 192, X + 96, XH + 96, XL + 96, 192);
        // 1x1 mixing
        k_mma<192, 192, 1, false, false><<<128, 256, SM_MX>>>(XH, XL, 192, mp + (size_t)blk * MP_PER_BLK, nullptr, nullptr, 0, Y, YH, YL, 192);
        float* tf = X; X = Y; Y = tf;
        __nv_bfloat16* th = XH; XH = YH; YH = th;
        __nv_bfloat16* tl = XL; XL = YL; YL = tl;
    }

    k_post<<<(NP * 192 + 255) / 256, 256>>>(X, out);
}

// round 10
// speedup vs baseline: 1.3325x; 1.0063x over previous
#include <cuda_runtime.h>
#include <cuda_bf16.h>
#include <cstdint>
#include <cstring>

// ---------------- constants ----------------
constexpr int NP = 8192;
constexpr int WTOT = 23592960;
constexpr int PER_BLK_W = 737280;
constexpr size_t WP_PER_BLK = 2949120;     // 4 bytes per weight (hi+lo bf16)
constexpr size_t MP_PER_BLK = 147456;

// ---------------- device scratch ----------------
__device__ char g_wpc[32 * WP_PER_BLK];
__device__ char g_mpc[32 * MP_PER_BLK];
__device__ float g_Xa[NP * 192], g_Xb[NP * 192];
__device__ __nv_bfloat16 g_XaH[NP * 192], g_XaL[NP * 192];
__device__ __nv_bfloat16 g_XbH[NP * 192], g_XbL[NP * 192];
__device__ __nv_bfloat16 g_T1H[NP * 128], g_T1L[NP * 128];
__device__ __nv_bfloat16 g_T2H[NP * 128], g_T2L[NP * 128];

// ---------------- helpers ----------------
__device__ __forceinline__ uint32_t smem_u32(const void* p) {
    uint32_t a;
    asm("{ .reg .u64 t; cvta.to.shared.u64 t, %1; cvt.u32.u64 %0, t; }" : "=r"(a) : "l"(p));
    return a;
}
__device__ __forceinline__ unsigned short f2bf(float v) {
    __nv_bfloat16 b = __float2bfloat16(v);
    unsigned short u; memcpy(&u, &b, 2);
    return u;
}
__device__ __forceinline__ float bf2f(unsigned short u) {
    __nv_bfloat16 b; memcpy(&b, &u, 2);
    return __bfloat162float(b);
}
__device__ __forceinline__ void ldm4(uint32_t* r, uint32_t addr) {
    asm volatile("ldmatrix.sync.aligned.m8n8.x4.shared.b16 {%0,%1,%2,%3}, [%4];"
        : "=r"(r[0]), "=r"(r[1]), "=r"(r[2]), "=r"(r[3]) : "r"(addr));
}
__device__ __forceinline__ void ldm2(uint32_t* r, uint32_t addr) {
    asm volatile("ldmatrix.sync.aligned.m8n8.x2.shared.b16 {%0,%1}, [%2];"
        : "=r"(r[0]), "=r"(r[1]) : "r"(addr));
}
__device__ __forceinline__ void mma16816(float* d, const uint32_t* a, uint32_t b0, uint32_t b1) {
    asm volatile("mma.sync.aligned.m16n8k16.row.col.f32.bf16.bf16.f32 "
        "{%0,%1,%2,%3},{%4,%5,%6,%7},{%8,%9},{%0,%1,%2,%3};"
        : "+f"(d[0]), "+f"(d[1]), "+f"(d[2]), "+f"(d[3])
        : "r"(a[0]), "r"(a[1]), "r"(a[2]), "r"(a[3]), "r"(b0), "r"(b1));
}
__device__ __forceinline__ void cpa16(uint32_t dst, const void* src, uint32_t srcsz) {
    asm volatile("cp.async.cg.shared.global [%0], [%1], 16, %2;"
        :: "r"(dst), "l"(src), "r"(srcsz) : "memory");
}
#define CP_COMMIT() asm volatile("cp.async.commit_group;" ::: "memory")
#define CP_WAIT0()  asm volatile("cp.async.wait_group 0;" ::: "memory")

// ---------------- weight prepack (convs) ----------------
// Per conv j, per tap: [hi OC x IC bf16][lo OC x IC bf16], dense rows.
__global__ void k_wp(const float* __restrict__ wf) {
    int idx = blockIdx.x * 256 + threadIdx.x;
    if (idx >= WTOT) return;
    int blk = idx / PER_BLK_W;
    int r = idx - blk * PER_BLK_W;
    const int starts[6] = {0, 110592, 258048, 368640, 479232, 626688};
    const size_t pre[6] = {0, 442368, 1032192, 1474560, 1916928, 2506752};
    int j = 0;
#pragma unroll
    for (int t = 1; t < 6; t++) if (r >= starts[t]) j = t;
    int off = r - starts[j];
    int oc = ((j % 3) == 2) ? 96 : 128;
    int ic = ((j % 3) == 0) ? 96 : 128;
    int o = off / (ic * 9);
    int rem = off - o * ic * 9;
    int c = rem / 9;
    int tap = rem - c * 9;
    float v = wf[idx];
    unsigned short hb = f2bf(v);
    unsigned short lb = f2bf(v - bf2f(hb));
    size_t base = (size_t)blk * WP_PER_BLK + pre[j] + (size_t)tap * (oc * ic * 4);
    size_t e = (size_t)(o * ic + c) * 2;
    *(unsigned short*)(g_wpc + base + e) = hb;
    *(unsigned short*)(g_wpc + base + (size_t)oc * ic * 2 + e) = lb;
}

// ---------------- mixing prepack: [hi 192x192][lo 192x192] ----------------
__global__ void k_mp(const float* __restrict__ m) {
    int idx = blockIdx.x * 256 + threadIdx.x;
    if (idx >= 32 * 36864) return;
    int blk = idx / 36864;
    int r = idx - blk * 36864;
    float v = m[idx];
    unsigned short hb = f2bf(v);
    unsigned short lb = f2bf(v - bf2f(hb));
    size_t base = (size_t)blk * MP_PER_BLK;
    *(unsigned short*)(g_mpc + base + (size_t)r * 2) = hb;
    *(unsigned short*)(g_mpc + base + 73728 + (size_t)r * 2) = lb;
}

// ---------------- normalize + permute + space_to_depth -> NHWC ----------------
__global__ void k_pre(const float* __restrict__ x, const float* __restrict__ mu,
                      const float* __restrict__ sigma, const int* __restrict__ perm,
                      float* __restrict__ Xo, __nv_bfloat16* __restrict__ XoH,
                      __nv_bfloat16* __restrict__ XoL) {
    int idx = blockIdx.x * 256 + threadIdx.x;
    if (idx >= NP * 192) return;
    int ch = idx % 192;
    int p = idx / 192;
    int w = p & 31, h = (p >> 5) & 31, b = p >> 10;
    int c = ch >> 6, r = ch & 63;
    int bi = r >> 3, bj = r & 7;
    int flat = (h * 8 + bi) * 256 + (w * 8 + bj);
    int src = perm[c * 65536 + flat];
    float v = (x[(b * 3 + c) * 65536 + src] - mu[c]) / sigma[c];
    Xo[idx] = v;
    unsigned short hb = f2bf(v);
    XoH[idx] = *(__nv_bfloat16*)&hb;
    unsigned short lb = f2bf(v - bf2f(hb));
    XoL[idx] = *(__nv_bfloat16*)&lb;
}

// ---------------- final NHWC -> NCHW ----------------
__global__ void k_post(const float* __restrict__ X, float* __restrict__ out) {
    int idx = blockIdx.x * 256 + threadIdx.x;
    if (idx >= NP * 192) return;
    int w = idx & 31;
    int h = (idx >> 5) & 31;
    int ch = (idx >> 10) % 192;
    int b = idx / (192 * 1024);
    out[idx] = X[(((b * 32 + h) * 32 + w) * 192) + ch];
}

// ---------------- warp-mma bf16x3 implicit-GEMM conv ----------------
// CTA = 64 positions x OCT columns (slice at nofs), 128 threads, 4 warps
// as 2M x 2N (warp = 32 rows x OCT/2 cols). Halo-A loaded once; per-stage
// B-only copy (NBUF buffers). smem < 113 KB -> 2 CTAs resident per SM.
template <int IC, int OC, int OCT, int KS, int NBUF, bool RELU, bool ADDIN>
__global__ __launch_bounds__(128, 2) void k_mma(
    const __nv_bfloat16* __restrict__ inH, const __nv_bfloat16* __restrict__ inL,
    int in_stride,
    const char* __restrict__ wp,
    const float* __restrict__ bias,
    const float* __restrict__ addp, int add_stride,
    float* __restrict__ out,
    __nv_bfloat16* __restrict__ outH, __nv_bfloat16* __restrict__ outL,
    int out_stride)
{
    constexpr int PH = KS / 2;
    constexpr int HR = 2 + 2 * PH;
    constexpr int HC = 32 + 2 * PH;
    constexpr int NPOS = HR * HC;
    constexpr int NST = KS * KS;
    constexpr int KST = IC / 16;
    constexpr int CPR = IC / 8;
    constexpr int LDC = IC + 8;
    constexpr int LDCb = LDC * 2;
    constexpr int WN = OCT / 2;          // warp N
    constexpr int NT = WN / 8;           // n8 tiles per warp
    constexpr int NP2 = NT / 2;
    constexpr int TAIL = NT & 1;
    constexpr int NSPL = OC / OCT;
    constexpr int ASZ = NPOS * LDC;      // b16 per A plane
    constexpr int BSZ = OCT * LDC;       // b16 per B plane buffer

    extern __shared__ __align__(16) unsigned short smem[];
    unsigned short* Ah = smem;
    unsigned short* Al = Ah + ASZ;
    unsigned short* Bh = Al + ASZ;
    unsigned short* Bl = Bh + NBUF * BSZ;

    const int tid = threadIdx.x;
    const int wid = tid >> 5, lane = tid & 31;
    const int wm = wid & 1, wn = wid >> 1;
    const int bx = blockIdx.x;
    const int tile = bx / NSPL;
    const int nofs = (bx - tile * NSPL) * OCT;
    const int p0 = tile * 64;
    const int b = p0 >> 10;
    const int h0 = (p0 >> 5) & 31;

    float acc[2][NT][4];
#pragma unroll
    for (int i = 0; i < 2; i++)
#pragma unroll
        for (int j = 0; j < NT; j++)
#pragma unroll
            for (int q = 0; q < 4; q++) acc[i][j][q] = 0.f;

    const uint32_t sAh = smem_u32(Ah), sAl = smem_u32(Al);
    const uint32_t sBh = smem_u32(Bh), sBl = smem_u32(Bl);

    // A fragment per-lane halo pixel offsets (bytes), one per mt
    uint32_t apix[2];
#pragma unroll
    for (int mt = 0; mt < 2; mt++) {
        int p = wm * 32 + mt * 16 + (lane & 15);
        apix[mt] = (uint32_t)(((p >> 5) * HC + (p & 31)) * LDCb) + ((lane >> 4) * 16);
    }

    // ---- prologue: A halo copy (once) ----
#pragma unroll 4
    for (int i = tid; i < NPOS * CPR; i += 128) {
        int pos = i / CPR, ck = i - pos * CPR;
        int hr = pos / HC, hc = pos - hr * HC;
        int hh = h0 + hr - PH, ww = hc - PH;
        bool ok = (hh >= 0) && (hh < 32) && (ww >= 0) && (ww < 32);
        size_t off = ok ? ((size_t)(((b << 5) + hh) * 32 + ww) * in_stride + ck * 8) : 0;
        uint32_t sz = ok ? 16u : 0u;
        uint32_t d = (uint32_t)(pos * LDC + ck * 8) * 2;
        cpa16(sAh + d, inH + off, sz);
        cpa16(sAl + d, inL + off, sz);
    }

    auto issueB = [&](int s, int buf) {
        const char* bu = wp + (size_t)s * (OC * IC * 4);
#pragma unroll
        for (int i = tid; i < OCT * CPR; i += 128) {
            int rr = i / CPR, ck = i - rr * CPR;
            size_t so = (size_t)((nofs + rr) * IC + ck * 8) * 2;
            uint32_t d = (uint32_t)(buf * BSZ + rr * LDC + ck * 8) * 2;
            cpa16(sBh + d, bu + so, 16);
            cpa16(sBl + d, bu + (size_t)OC * IC * 2 + so, 16);
        }
        CP_COMMIT();
    };

    issueB(0, 0);   // commits A + B0 together

    for (int s = 0; s < NST; s++) {
        CP_WAIT0();
        __syncthreads();
        if (NBUF == 2 && s + 1 < NST) issueB(s + 1, (s + 1) & 1);

        const int cb = (NBUF == 2) ? (s & 1) : 0;
        const uint32_t hoffb = (uint32_t)(((s / KS) * HC + (s - (s / KS) * KS)) * LDCb);
        const uint32_t aAh = sAh + hoffb;
        const uint32_t aAl = sAl + hoffb;
        const uint32_t aBh = sBh + (uint32_t)(cb * BSZ) * 2;
        const uint32_t aBl = sBl + (uint32_t)(cb * BSZ) * 2;

        uint32_t fah[2][2][4], fal[2][2][4];
        uint32_t fbh[2][NP2 ? NP2 : 1][4], fbl[2][NP2 ? NP2 : 1][4];
        uint32_t fth[2][2], ftl[2][2];

        auto ldfrag = [&](int ks, int fb) {
#pragma unroll
            for (int mt = 0; mt < 2; mt++) {
                uint32_t ro = apix[mt] + (uint32_t)ks * 32;
                ldm4(fah[fb][mt], aAh + ro);
                ldm4(fal[fb][mt], aAl + ro);
            }
#pragma unroll
            for (int p = 0; p < NP2; p++) {
                uint32_t ro = (uint32_t)(wn * WN + p * 16 + (lane & 15)) * LDCb
                            + (uint32_t)ks * 32 + ((lane >> 4) * 16);
                ldm4(fbh[fb][p], aBh + ro);
                ldm4(fbl[fb][p], aBl + ro);
            }
            if (TAIL) {
                uint32_t ro = (uint32_t)(wn * WN + NP2 * 16 + (lane & 7)) * LDCb
                            + (uint32_t)ks * 32 + (((lane >> 3) & 1) * 16);
                ldm2(fth[fb], aBh + ro);
                ldm2(ftl[fb], aBl + ro);
            }
        };

        ldfrag(0, 0);
#pragma unroll
        for (int ks = 0; ks < KST; ks++) {
            if (ks + 1 < KST) ldfrag(ks + 1, (ks + 1) & 1);
            const int fb = ks & 1;
#pragma unroll
            for (int p = 0; p < NP2; p++) {
#pragma unroll
                for (int sub = 0; sub < 2; sub++) {
#pragma unroll
                    for (int mt = 0; mt < 2; mt++) {
                        float* d = acc[mt][p * 2 + sub];
                        mma16816(d, fah[fb][mt], fbh[fb][p][sub], fbh[fb][p][sub + 2]);
                        mma16816(d, fah[fb][mt], fbl[fb][p][sub], fbl[fb][p][sub + 2]);
                        mma16816(d, fal[fb][mt], fbh[fb][p][sub], fbh[fb][p][sub + 2]);
                    }
                }
            }
            if (TAIL) {
#pragma unroll
                for (int mt = 0; mt < 2; mt++) {
                    float* d = acc[mt][NT - 1];
                    mma16816(d, fah[fb][mt], fth[fb][0], fth[fb][1]);
                    mma16816(d, fah[fb][mt], ftl[fb][0], ftl[fb][1]);
                    mma16816(d, fal[fb][mt], fth[fb][0], fth[fb][1]);
                }
            }
        }

        if (NBUF == 1 && s + 1 < NST) {
            __syncthreads();            // all warps done reading B buffer
            issueB(s + 1, 0);
        }
    }

    // ---- epilogue ----
    const int l4 = lane >> 2, l2 = (lane & 3) * 2;
#pragma unroll
    for (int nt = 0; nt < NT; nt++) {
        const int col = nofs + wn * WN + nt * 8 + l2;
        float b0 = 0.f, b1 = 0.f;
        if (bias) { b0 = bias[col]; b1 = bias[col + 1]; }
#pragma unroll
        for (int mt = 0; mt < 2; mt++) {
            const int pr = p0 + wm * 32 + mt * 16 + l4;
            float* d = acc[mt][nt];
            float v0 = d[0] + b0, v1 = d[1] + b1, v2 = d[2] + b0, v3 = d[3] + b1;
            if (RELU) {
                v0 = fmaxf(v0, 0.f); v1 = fmaxf(v1, 0.f);
                v2 = fmaxf(v2, 0.f); v3 = fmaxf(v3, 0.f);
            }
            if (ADDIN) {
                float2 a0 = *(const float2*)(addp + (size_t)pr * add_stride + col);
                float2 a1 = *(const float2*)(addp + (size_t)(pr + 8) * add_stride + col);
                v0 += a0.x; v1 += a0.y; v2 += a1.x; v3 += a1.y;
            }
            if (out) {
                *(float2*)(out + (size_t)pr * out_stride + col) = make_float2(v0, v1);
                *(float2*)(out + (size_t)(pr + 8) * out_stride + col) = make_float2(v2, v3);
            }
            __nv_bfloat162 h01 = __float22bfloat162_rn(make_float2(v0, v1));
            __nv_bfloat162 h23 = __float22bfloat162_rn(make_float2(v2, v3));
            float2 f01 = __bfloat1622float2(h01);
            float2 f23 = __bfloat1622float2(h23);
            __nv_bfloat162 l01 = __float22bfloat162_rn(make_float2(v0 - f01.x, v1 - f01.y));
            __nv_bfloat162 l23 = __float22bfloat162_rn(make_float2(v2 - f23.x, v3 - f23.y));
            *(__nv_bfloat162*)(outH + (size_t)pr * out_stride + col) = h01;
            *(__nv_bfloat162*)(outH + (size_t)(pr + 8) * out_stride + col) = h23;
            *(__nv_bfloat162*)(outL + (size_t)pr * out_stride + col) = l01;
            *(__nv_bfloat162*)(outL + (size_t)(pr + 8) * out_stride + col) = l23;
        }
    }
}

// ---------------- launch ----------------
extern "C" void kernel_launch(void* const* d_in, const int* in_sizes, int n_in,
                              void* d_out, int out_size) {
    const float* x     = (const float*)d_in[0];
    const float* mu    = (const float*)d_in[1];
    const float* sigma = (const float*)d_in[2];
    const float* wf    = (const float*)d_in[3];
    const float* bfl   = (const float*)d_in[4];
    const float* m     = (const float*)d_in[5];
    const int*   perm  = (const int*)d_in[6];
    float* out = (float*)d_out;

    char *wp, *mp;
    float *Xa, *Xb;
    __nv_bfloat16 *XaH, *XaL, *XbH, *XbL, *T1H, *T1L, *T2H, *T2L;
    cudaGetSymbolAddress((void**)&wp, g_wpc);
    cudaGetSymbolAddress((void**)&mp, g_mpc);
    cudaGetSymbolAddress((void**)&Xa, g_Xa);
    cudaGetSymbolAddress((void**)&Xb, g_Xb);
    cudaGetSymbolAddress((void**)&XaH, g_XaH);
    cudaGetSymbolAddress((void**)&XaL, g_XaL);
    cudaGetSymbolAddress((void**)&XbH, g_XbH);
    cudaGetSymbolAddress((void**)&XbL, g_XbL);
    cudaGetSymbolAddress((void**)&T1H, g_T1H);
    cudaGetSymbolAddress((void**)&T1L, g_T1L);
    cudaGetSymbolAddress((void**)&T2H, g_T2H);
    cudaGetSymbolAddress((void**)&T2L, g_T2L);

    // dynamic smem bytes: 4*NPOS*LDC + NBUF*4*OCT*LDC
    const int SM_C1 = 4 * (136 * 104) + 2 * 4 * (64 * 104);   // 109,824
    const int SM_C2 = 4 * (136 * 136) + 1 * 4 * (64 * 136);   // 108,800
    const int SM_C3 = 4 * (136 * 136) + 1 * 4 * (48 * 136);   // 100,096
    const int SM_MX = 4 * (64 * 200) + 1 * 4 * (64 * 200);    // 102,400
    static bool attr_done = false;
    if (!attr_done) {
        cudaFuncSetAttribute(k_mma<96, 128, 64, 3, 2, true, false>,  cudaFuncAttributeMaxDynamicSharedMemorySize, SM_C1);
        cudaFuncSetAttribute(k_mma<128, 128, 64, 3, 1, true, false>, cudaFuncAttributeMaxDynamicSharedMemorySize, SM_C2);
        cudaFuncSetAttribute(k_mma<128, 96, 48, 3, 1, false, true>,  cudaFuncAttributeMaxDynamicSharedMemorySize, SM_C3);
        cudaFuncSetAttribute(k_mma<192, 192, 64, 1, 1, false, false>, cudaFuncAttributeMaxDynamicSharedMemorySize, SM_MX);
        attr_done = true;
    }

    k_wp<<<(WTOT + 255) / 256, 256>>>(wf);
    k_mp<<<(32 * 36864 + 255) / 256, 256>>>(m);
    k_pre<<<(NP * 192 + 255) / 256, 256>>>(x, mu, sigma, perm, Xa, XaH, XaL);

    const size_t pre_j[6] = {0, 442368, 1032192, 1474560, 1916928, 2506752};
    const int bstart[6] = {0, 128, 256, 352, 480, 608};

    float* X = Xa;  __nv_bfloat16 *XH = XaH, *XL = XaL;
    float* Y = Xb;  __nv_bfloat16 *YH = XbH, *YL = XbL;
    for (int blk = 0; blk < 32; blk++) {
        const char* wb = wp + (size_t)blk * WP_PER_BLK;
        const float* bb = bfl + blk * 704;
        // round 0: x1 += f0(x2)
        k_mma<96, 128, 64, 3, 2, true, false><<<256, 128, SM_C1>>>(XH + 96, XL + 96, 192, wb + pre_j[0], bb + bstart[0], nullptr, 0, nullptr, T1H, T1L, 128);
        k_mma<128, 128, 64, 3, 1, true, false><<<256, 128, SM_C2>>>(T1H, T1L, 128, wb + pre_j[1], bb + bstart[1], nullptr, 0, nullptr, T2H, T2L, 128);
        k_mma<128, 96, 48, 3, 1, false, true><<<256, 128, SM_C3>>>(T2H, T2L, 128, wb + pre_j[2], bb + bstart[2], X + 0, 192, X + 0, XH + 0, XL + 0, 192);
        // round 1: x2 += f1(x1)
        k_mma<96, 128, 64, 3, 2, true, false><<<256, 128, SM_C1>>>(XH + 0, XL + 0, 192, wb + pre_j[3], bb + bstart[3], nullptr, 0, nullptr, T1H, T1L, 128);
        k_mma<128, 128, 64, 3, 1, true, false><<<256, 128, SM_C2>>>(T1H, T1L, 128, wb + pre_j[4], bb + bstart[4], nullptr, 0, nullptr, T2H, T2L, 128);
        k_mma<128, 96, 48, 3, 1, false, true><<<256, 128, SM_C3>>>(T2H, T2L, 128, wb + pre_j[5], bb + bstart[5], X + 96, 192, X + 96, XH + 96, XL + 96, 192);
        // 1x1 mixing
        k_mma<192, 192, 64, 1, 1, false, false><<<384, 128, SM_MX>>>(XH, XL, 192, mp + (size_t)blk * MP_PER_BLK, nullptr, nullptr, 0, Y, YH, YL, 192);
        float* tf = X; X = Y; Y = tf;
        __nv_bfloat16* th = XH; XH = YH; YH = th;
        __nv_bfloat16* tl = XL; XL = YL; YL = tl;
    }

    k_post<<<(NP * 192 + 255) / 256, 256>>>(X, out);
}